// round 9
// baseline (speedup 1.0000x reference)
#include <cuda_runtime.h>

// Fixed problem shape: N=50000, E=800000, F=64, IN=128
#define NN_MAX 50000
#define NE_MAX 800000
#define ET_MAX (NE_MAX + NN_MAX)

// ---------------- scratch (static device globals; no allocation) -------------
__device__ __align__(16) float g_xl[NN_MAX * 64];
__device__ __align__(16) float g_xr[NN_MAX * 64];
__device__ __align__(16) float g_h [NN_MAX * 64];
__device__ int   g_srcs[ET_MAX];   // src ids sorted by dst (CSR adjacency)
__device__ int   g_cnt[NN_MAX];    // in-degree (incl self loop)
__device__ int   g_row[NN_MAX];    // CSR row offsets
__device__ int   g_cur[NN_MAX];    // scatter cursors

// ---------------- CSR build --------------------------------------------------
__global__ void zero_cnt(int n) {
    int i = blockIdx.x * blockDim.x + threadIdx.x;
    if (i < n) g_cnt[i] = 0;
}

// int32 edge_index (JAX x64 disabled). Clamp defensively; self loops add 1 each.
__global__ void prep_hist(const int* __restrict__ ei, int E, int n) {
    int i = blockIdx.x * blockDim.x + threadIdx.x;
    if (i < E) {
        int d = ei[E + i];
        d = min(max(d, 0), n - 1);
        atomicAdd(&g_cnt[d], 1);
    }
    if (i < n) atomicAdd(&g_cnt[i], 1);
}

// single-block exclusive scan of g_cnt -> g_row; zero g_cur. 1024 thr, 49 elem/thr.
__global__ __launch_bounds__(1024) void scan_fused(int n) {
    __shared__ int sm[1024];
    const int t = threadIdx.x;
    const int per = (n + 1023) >> 10;          // 49
    const int base = t * per;
    int local = 0;
    for (int i = 0; i < per; i++) {
        int idx = base + i;
        if (idx < n) local += g_cnt[idx];
    }
    sm[t] = local; __syncthreads();
    for (int off = 1; off < 1024; off <<= 1) {
        int v = (t >= off) ? sm[t - off] : 0;
        __syncthreads();
        sm[t] += v; __syncthreads();
    }
    int run = sm[t] - local;                   // exclusive prefix
    for (int i = 0; i < per; i++) {
        int idx = base + i;
        if (idx < n) {
            g_row[idx] = run;
            g_cur[idx] = 0;
            run += g_cnt[idx];
        }
    }
}

__global__ void scatter(const int* __restrict__ ei, int E, int n) {
    int i = blockIdx.x * blockDim.x + threadIdx.x;
    if (i < E) {
        int s = ei[i], d = ei[E + i];
        s = min(max(s, 0), n - 1);
        d = min(max(d, 0), n - 1);
        int pos = g_row[d] + atomicAdd(&g_cur[d], 1);
        g_srcs[pos] = s;
    }
    if (i < n) {
        int pos = g_row[i] + atomicAdd(&g_cur[i], 1);
        g_srcs[pos] = i;
    }
}

// ---------------- dual GEMM: XL = X@Wl, XR = X@Wr  (Wl,Wr: [K,64]) -----------
// 64 rows/block, 256 threads: 16 row-threads x 4 rows, 16 col-groups x 8 cols.
// 32 FMA per (2 LDG + 4 LDS) per k -> FMA-bound.
template <int K>
__global__ __launch_bounds__(256) void gemm_dual(const float* Xin,
                          const float* __restrict__ Wl,
                          const float* __restrict__ Wr,
                          int n) {
    const float* __restrict__ X = Xin ? Xin : g_h;
    __shared__ float xs[64][K + 4];
    const int row0 = blockIdx.x * 64;
    const int t = threadIdx.x;

    for (int i = t; i < 64 * K; i += 256) {
        int r = i / K, k = i - r * K;
        int gr = row0 + r;
        xs[r][k] = (gr < n) ? X[gr * K + k] : 0.0f;
    }
    __syncthreads();

    const int rs = t >> 4;              // 0..15 -> rows 4*rs .. 4*rs+3
    const int cg = t & 15;
    const float* __restrict__ W = (cg < 8) ? Wl : Wr;
    const int c0 = (cg & 7) * 8;

    float acc[4][8];
#pragma unroll
    for (int r = 0; r < 4; r++)
#pragma unroll
        for (int j = 0; j < 8; j++) acc[r][j] = 0.0f;

#pragma unroll 4
    for (int k = 0; k < K; k++) {
        float4 w0 = __ldg((const float4*)&W[k * 64 + c0]);
        float4 w1 = __ldg((const float4*)&W[k * 64 + c0 + 4]);
#pragma unroll
        for (int r = 0; r < 4; r++) {
            float xv = xs[4 * rs + r][k];
            acc[r][0] = fmaf(xv, w0.x, acc[r][0]);
            acc[r][1] = fmaf(xv, w0.y, acc[r][1]);
            acc[r][2] = fmaf(xv, w0.z, acc[r][2]);
            acc[r][3] = fmaf(xv, w0.w, acc[r][3]);
            acc[r][4] = fmaf(xv, w1.x, acc[r][4]);
            acc[r][5] = fmaf(xv, w1.y, acc[r][5]);
            acc[r][6] = fmaf(xv, w1.z, acc[r][6]);
            acc[r][7] = fmaf(xv, w1.w, acc[r][7]);
        }
    }

    float* __restrict__ O = (cg < 8) ? g_xl : g_xr;
#pragma unroll
    for (int r = 0; r < 4; r++) {
        int gr = row0 + 4 * rs + r;
        if (gr < n) {
            *(float4*)&O[gr * 64 + c0]     = make_float4(acc[r][0], acc[r][1], acc[r][2], acc[r][3]);
            *(float4*)&O[gr * 64 + c0 + 4] = make_float4(acc[r][4], acc[r][5], acc[r][6], acc[r][7]);
        }
    }
}

// ---------------- single-pass fused GATv2 node kernel ------------------------
// Warp per node, two 16-lane halves; 8 edges per warp iteration (4 per half,
// 4 independent gathers in flight). Flash-style online softmax+aggregation.
__device__ __forceinline__ float dot_leaky(float4 a, float4 xr, float4 av) {
    float ux = a.x + xr.x; ux = (ux > 0.0f) ? ux : 0.2f * ux;
    float uy = a.y + xr.y; uy = (uy > 0.0f) ? uy : 0.2f * uy;
    float uz = a.z + xr.z; uz = (uz > 0.0f) ? uz : 0.2f * uz;
    float uw = a.w + xr.w; uw = (uw > 0.0f) ? uw : 0.2f * uw;
    return fmaf(ux, av.x, fmaf(uy, av.y, fmaf(uz, av.z, uw * av.w)));
}

__global__ __launch_bounds__(256) void node_fused(const float* __restrict__ att,
                           const float* __restrict__ bias,
                           float* outp, int do_relu, int n) {
    float* __restrict__ out = outp ? outp : g_h;
    int node = (blockIdx.x * blockDim.x + threadIdx.x) >> 5;
    if (node >= n) return;
    const int lane = threadIdx.x & 31;
    const int half = lane >> 4;
    const int hl   = lane & 15;

    const int beg = g_row[node];
    const int deg = g_cnt[node];
    const int end = beg + deg;

    const float4 xr4 = *(const float4*)&g_xr[node * 64 + hl * 4];
    const float4 av4 = *(const float4*)&att[hl * 4];

    float m = -1e30f, ssum = 0.0f;
    float4 acc = make_float4(0.0f, 0.0f, 0.0f, 0.0f);

    for (int kk = 0; kk < deg; kk += 8) {
        int   idx[4];
        bool  vv[4];
        int   ss[4];
        float4 aa[4];
#pragma unroll
        for (int j = 0; j < 4; j++) {
            idx[j] = beg + kk + 2 * j + half;
            vv[j]  = idx[j] < end;
            ss[j]  = g_srcs[vv[j] ? idx[j] : beg];
        }
#pragma unroll
        for (int j = 0; j < 4; j++)
            aa[j] = *(const float4*)&g_xl[ss[j] * 64 + hl * 4];

        float p[4];
#pragma unroll
        for (int j = 0; j < 4; j++) p[j] = dot_leaky(aa[j], xr4, av4);
#pragma unroll
        for (int o = 1; o < 16; o <<= 1) {
#pragma unroll
            for (int j = 0; j < 4; j++)
                p[j] += __shfl_xor_sync(0xffffffffu, p[j], o);
        }

        float mn = m;
#pragma unroll
        for (int j = 0; j < 4; j++) {
            float q = vv[j] ? p[j] : -3.402823e38f;
            mn = fmaxf(mn, q);
        }
        float sc = __expf(m - mn);
        float e[4];
#pragma unroll
        for (int j = 0; j < 4; j++) e[j] = vv[j] ? __expf(p[j] - mn) : 0.0f;

        ssum = fmaf(ssum, sc, (e[0] + e[1]) + (e[2] + e[3]));
        acc.x = fmaf(acc.x, sc, fmaf(e[0], aa[0].x, fmaf(e[1], aa[1].x, fmaf(e[2], aa[2].x, e[3] * aa[3].x))));
        acc.y = fmaf(acc.y, sc, fmaf(e[0], aa[0].y, fmaf(e[1], aa[1].y, fmaf(e[2], aa[2].y, e[3] * aa[3].y))));
        acc.z = fmaf(acc.z, sc, fmaf(e[0], aa[0].z, fmaf(e[1], aa[1].z, fmaf(e[2], aa[2].z, e[3] * aa[3].z))));
        acc.w = fmaf(acc.w, sc, fmaf(e[0], aa[0].w, fmaf(e[1], aa[1].w, fmaf(e[2], aa[2].w, e[3] * aa[3].w))));
        m = mn;
    }

    // combine halves (shfl_xor 16 symmetric)
    float m2 = __shfl_xor_sync(0xffffffffu, m, 16);
    float s2 = __shfl_xor_sync(0xffffffffu, ssum, 16);
    float4 ac2;
    ac2.x = __shfl_xor_sync(0xffffffffu, acc.x, 16);
    ac2.y = __shfl_xor_sync(0xffffffffu, acc.y, 16);
    ac2.z = __shfl_xor_sync(0xffffffffu, acc.z, 16);
    ac2.w = __shfl_xor_sync(0xffffffffu, acc.w, 16);
    float mn = fmaxf(m, m2);
    float c1 = __expf(m - mn), c2 = __expf(m2 - mn);
    ssum = ssum * c1 + s2 * c2;
    acc.x = acc.x * c1 + ac2.x * c2;
    acc.y = acc.y * c1 + ac2.y * c2;
    acc.z = acc.z * c1 + ac2.z * c2;
    acc.w = acc.w * c1 + ac2.w * c2;

    const float inv = 1.0f / (ssum + 1e-16f);
    float4 b4 = *(const float4*)&bias[hl * 4];
    float4 r;
    r.x = fmaf(acc.x, inv, b4.x);
    r.y = fmaf(acc.y, inv, b4.y);
    r.z = fmaf(acc.z, inv, b4.z);
    r.w = fmaf(acc.w, inv, b4.w);
    if (do_relu) {
        r.x = fmaxf(r.x, 0.0f); r.y = fmaxf(r.y, 0.0f);
        r.z = fmaxf(r.z, 0.0f); r.w = fmaxf(r.w, 0.0f);
    }
    if (half == 0) *(float4*)&out[node * 64 + hl * 4] = r;
}

// ---------------- launch ------------------------------------------------------
extern "C" void kernel_launch(void* const* d_in, const int* in_sizes, int n_in,
                              void* d_out, int out_size) {
    const float* x    = (const float*)d_in[0];
    const int*   ei   = (const int*)d_in[1];    // int32 (JAX x64 disabled)
    const float* W1l  = (const float*)d_in[2];
    const float* W1r  = (const float*)d_in[3];
    const float* att1 = (const float*)d_in[4];
    const float* b1   = (const float*)d_in[5];
    const float* W2l  = (const float*)d_in[6];
    const float* W2r  = (const float*)d_in[7];
    const float* att2 = (const float*)d_in[8];
    const float* b2   = (const float*)d_in[9];

    const int n = in_sizes[0] / 128;   // 50000
    const int E = in_sizes[1] / 2;     // 800000

    float* out = (float*)d_out;
    const int B = 256;

    // ---- CSR build (4 launches) ----
    zero_cnt<<<(n + B - 1) / B, B>>>(n);
    prep_hist<<<(E + B - 1) / B, B>>>(ei, E, n);
    scan_fused<<<1, 1024>>>(n);
    scatter<<<(E + B - 1) / B, B>>>(ei, E, n);

    const int gridNode = (n * 32 + B - 1) / B;

    // ---- layer 1 ----
    gemm_dual<128><<<(n + 63) / 64, 256>>>(x, W1l, W1r, n);
    node_fused<<<gridNode, B>>>(att1, b1, nullptr, 1, n);

    // ---- layer 2 ----
    gemm_dual<64><<<(n + 63) / 64, 256>>>(nullptr, W2l, W2r, n);
    node_fused<<<gridNode, B>>>(att2, b2, out, 0, n);
}